// round 13
// baseline (speedup 1.0000x reference)
#include <cuda_runtime.h>
#include <cooperative_groups.h>
namespace cg = cooperative_groups;

#define H 4096
#define NIN 17
#define NA 4
#define CSIZE 8            // CTAs per cluster
#define COLS 32            // columns per cluster (full 128B line)
#define ROWS 512           // rows per CTA (8 * 512 = 4096)
#define T 512
#define STRIDE 36          // padded smem row stride in floats

// smem layout (dynamic, floats):
#define OFF_HEBB   0
#define OFF_HIDDEN (ROWS * STRIDE)                 // + ROWS
#define OFF_RED    (OFF_HIDDEN + ROWS)             // + 16*32
#define OFF_CROSS  (OFF_RED + 16 * 32)             // + CSIZE*32
#define OFF_HV     (OFF_CROSS + CSIZE * 32)        // + 32
#define SMEM_FLOATS (OFF_HV + 32)

__device__ __align__(16) float g_h[H];
__device__ float g_logits[NA + 1];

__global__ void __cluster_dims__(CSIZE, 1, 1) __launch_bounds__(T, 2)
fused_cluster(const float* __restrict__ x,
              const float* __restrict__ hidden,
              const float* __restrict__ hebb,
              const float* __restrict__ i2h_w,
              const float* __restrict__ i2h_b,
              const float* __restrict__ w,
              const float* __restrict__ alpha,
              const float* __restrict__ eta,
              float* __restrict__ out)
{
    extern __shared__ float sh[];
    float* sh_hebb   = sh + OFF_HEBB;
    float* sh_hidden = sh + OFF_HIDDEN;
    float* sh_red    = sh + OFF_RED;
    float* sh_cross  = sh + OFF_CROSS;
    float* sh_hv     = sh + OFF_HV;

    cg::cluster_group cluster = cg::this_cluster();
    const unsigned rank = cluster.block_rank();

    const int tid  = threadIdx.x;
    const int q    = tid & 3;          // 8-col chunk within the 32 cols
    const int rloc = tid >> 2;         // 0..127 row lane
    const int warp = tid >> 5;
    const int lane = tid & 31;
    const int jb   = (blockIdx.x / CSIZE) * COLS;   // cluster column base
    const int i0   = (int)rank * ROWS;              // this CTA's row base
    const float eta_v = __ldg(eta);

    // preamble: this CTA's hidden slice (512 rows)
    sh_hidden[tid] = hidden[i0 + tid];
    __syncthreads();

    const float4* __restrict__ w4 = (const float4*)w;
    const float4* __restrict__ a4 = (const float4*)alpha;
    const float4* __restrict__ b4 = (const float4*)hebb;

    // ---- Phase 1: stream w/alpha/hebb strip; stash hebb in SMEM; partials ----
    float acc[8] = {0.f, 0.f, 0.f, 0.f, 0.f, 0.f, 0.f, 0.f};
    #pragma unroll
    for (int pass = 0; pass < ROWS / 128; ++pass) {     // 4 passes
        const int il = rloc + pass * 128;
        const size_t o4 = ((size_t)(i0 + il) * H + jb + q * 8) >> 2;
        const float4 w0 = __ldg(w4 + o4),     w1 = __ldg(w4 + o4 + 1);
        const float4 a0 = __ldg(a4 + o4),     a1 = __ldg(a4 + o4 + 1);
        const float4 b0 = __ldg(b4 + o4),     b1 = __ldg(b4 + o4 + 1);
        float4* s = (float4*)&sh_hebb[il * STRIDE + q * 8];
        s[0] = b0;
        s[1] = b1;
        const float hv = sh_hidden[il];
        acc[0] = fmaf(hv, fmaf(a0.x, b0.x, w0.x), acc[0]);
        acc[1] = fmaf(hv, fmaf(a0.y, b0.y, w0.y), acc[1]);
        acc[2] = fmaf(hv, fmaf(a0.z, b0.z, w0.z), acc[2]);
        acc[3] = fmaf(hv, fmaf(a0.w, b0.w, w0.w), acc[3]);
        acc[4] = fmaf(hv, fmaf(a1.x, b1.x, w1.x), acc[4]);
        acc[5] = fmaf(hv, fmaf(a1.y, b1.y, w1.y), acc[5]);
        acc[6] = fmaf(hv, fmaf(a1.z, b1.z, w1.z), acc[6]);
        acc[7] = fmaf(hv, fmaf(a1.w, b1.w, w1.w), acc[7]);
    }
    // warp reduce over the 8 row-lanes (xor 4/8/16 keeps q = lane&3)
    #pragma unroll
    for (int o = 4; o <= 16; o <<= 1)
        #pragma unroll
        for (int c = 0; c < 8; ++c)
            acc[c] += __shfl_xor_sync(0xffffffffu, acc[c], o);
    if (lane < 4) {
        #pragma unroll
        for (int c = 0; c < 8; ++c)
            sh_red[warp * 32 + lane * 8 + c] = acc[c];
    }
    __syncthreads();

    // CTA partial per column -> leader's sh_cross via DSMEM (write-before-sync is safe)
    if (tid < COLS) {
        float s = 0.f;
        #pragma unroll
        for (int wp = 0; wp < 16; ++wp) s += sh_red[wp * 32 + tid];
        float* dst = cluster.map_shared_rank(sh_cross, 0);
        dst[rank * COLS + tid] = s;
    }
    cluster.sync();

    // leader: final reduce across 8 ranks + i2h + tanh -> h, then PUSH h to all ranks.
    // (Push, not pull: after the next cluster.sync no CTA touches remote SMEM,
    //  so there is no use-after-exit race on peer shared memory.)
    if (rank == 0 && tid < COLS) {
        float s = 0.f;
        #pragma unroll
        for (int rr = 0; rr < CSIZE; ++rr) s += sh_cross[rr * COLS + tid];
        const int j = jb + tid;
        float pr = i2h_b[j];
        #pragma unroll
        for (int kk = 0; kk < NIN; ++kk)
            pr = fmaf(x[kk], i2h_w[j * NIN + kk], pr);
        const float hj = tanhf(pr + s);
        g_h[j]     = hj;
        out[5 + j] = hj;
        #pragma unroll
        for (int rr = 0; rr < CSIZE; ++rr) {
            float* dst = cluster.map_shared_rank(sh_hv, rr);
            dst[tid] = hj;
        }
    }
    cluster.sync();
    // from here on: only local SMEM and global memory — no DSMEM.

    // ---- Phase 3: hebb_new from SMEM stash (no gmem re-read) ----
    const float om = 1.f - eta_v;
    const int  c3  = tid & 31;         // column (warp = 32 consecutive cols = 128B)
    const int  r3  = tid >> 5;         // 0..15 row lane
    const float hj = sh_hv[c3];
    float* __restrict__ outp = out + 5 + H;     // 4B-misaligned -> scalar stores

    #pragma unroll 8
    for (int it = 0; it < ROWS / 16; ++it) {
        const int il = r3 + it * 16;
        const float hb = sh_hebb[il * STRIDE + c3];
        const size_t idx = (size_t)(i0 + il) * H + jb + c3;
        __stcs(outp + idx, fmaf(om, hb, eta_v * sh_hidden[il] * hj));
    }
}

// ---- heads: 5 blocks, one logit each (fixed-order deterministic reduce) ----
__global__ __launch_bounds__(512)
void k_heads(const float* __restrict__ h2o_w,
             const float* __restrict__ h2o_b,
             const float* __restrict__ h2v_w,
             const float* __restrict__ h2v_b)
{
    __shared__ float red[16];
    const int a = blockIdx.x;
    const int tid = threadIdx.x, warp = tid >> 5, lane = tid & 31;
    const float* row = (a < NA) ? (h2o_w + (size_t)a * H) : h2v_w;
    float s = 0.f;
    #pragma unroll
    for (int k = 0; k < H / 512; ++k) {
        const int j = tid + k * 512;
        s = fmaf(g_h[j], row[j], s);
    }
    #pragma unroll
    for (int o = 16; o; o >>= 1) s += __shfl_xor_sync(0xffffffffu, s, o);
    if (lane == 0) red[warp] = s;
    __syncthreads();
    if (tid == 0) {
        float t = (a < NA) ? h2o_b[a] : h2v_b[0];
        #pragma unroll
        for (int wp = 0; wp < 16; ++wp) t += red[wp];
        g_logits[a] = t;
    }
}

// ---- finisher: softmax + value ----
__global__ void k_fin(float* __restrict__ out)
{
    if (threadIdx.x == 0) {
        float lg[NA];
        #pragma unroll
        for (int a = 0; a < NA; ++a) lg[a] = g_logits[a];
        float m = lg[0];
        #pragma unroll
        for (int a = 1; a < NA; ++a) m = fmaxf(m, lg[a]);
        float e[NA], se = 0.f;
        #pragma unroll
        for (int a = 0; a < NA; ++a) { e[a] = expf(lg[a] - m); se += e[a]; }
        const float inv = 1.f / se;
        #pragma unroll
        for (int a = 0; a < NA; ++a) out[a] = e[a] * inv;
        out[NA] = g_logits[NA];
    }
}

extern "C" void kernel_launch(void* const* d_in, const int* in_sizes, int n_in,
                              void* d_out, int out_size)
{
    const float* x      = (const float*)d_in[0];
    const float* hidden = (const float*)d_in[1];
    const float* hebb   = (const float*)d_in[2];
    const float* i2h_w  = (const float*)d_in[3];
    const float* i2h_b  = (const float*)d_in[4];
    const float* w      = (const float*)d_in[5];
    const float* alpha  = (const float*)d_in[6];
    const float* eta    = (const float*)d_in[7];
    const float* h2o_w  = (const float*)d_in[8];
    const float* h2o_b  = (const float*)d_in[9];
    const float* h2v_w  = (const float*)d_in[10];
    const float* h2v_b  = (const float*)d_in[11];
    float* out = (float*)d_out;

    const size_t smem = SMEM_FLOATS * sizeof(float);   // ~78 KB -> 2 CTAs/SM
    cudaFuncSetAttribute(fused_cluster,
                         cudaFuncAttributeMaxDynamicSharedMemorySize, (int)smem);

    fused_cluster<<<(H / COLS) * CSIZE, T, smem>>>(x, hidden, hebb, i2h_w, i2h_b,
                                                   w, alpha, eta, out);
    k_heads<<<NA + 1, 512>>>(h2o_w, h2o_b, h2v_w, h2v_b);
    k_fin<<<1, 32>>>(out);
}

// round 14
// speedup vs baseline: 1.0273x; 1.0273x over previous
#include <cuda_runtime.h>

#define H 4096
#define NIN 17
#define NA 4

#define GRID1 256           // K1: 16 rows per block -> single wave at 2 CTA/SM
#define T1 512
#define NPART GRID1
#define GRID2 128           // K2: 32 cols per block
#define T2 512
#define GRID3 1024          // K3: 16384 elements per block (+1 head block)
#define T3 512

// persistent device scratch (static globals allowed; no runtime alloc)
__device__ float4 g_scratch4[NPART * H / 4];   // [p][col/4] partials, 4 MiB
__device__ __align__(16) float g_h[H];         // aligned shadow of h

// ============ K1: partial sums of hidden @ (w + alpha*hebb), 16 rows/block ============
__global__ __launch_bounds__(T1)
void k1_partials(const float* __restrict__ hidden,
                 const float* __restrict__ w,
                 const float* __restrict__ alpha,
                 const float* __restrict__ hebb)
{
    const int tid = threadIdx.x;
    const int p   = blockIdx.x;
    const int i0  = p * 16;
    const int c0  = tid * 8;          // this thread's 8-column chunk (32B aligned)

    const float4* __restrict__ w4 = (const float4*)w;
    const float4* __restrict__ a4 = (const float4*)alpha;
    const float4* __restrict__ b4 = (const float4*)hebb;

    float acc[8] = {0.f, 0.f, 0.f, 0.f, 0.f, 0.f, 0.f, 0.f};
    #pragma unroll 8
    for (int r = 0; r < 16; ++r) {
        const float hv = __ldg(&hidden[i0 + r]);
        const size_t o4 = ((size_t)(i0 + r) * H + c0) >> 2;
        const float4 w0 = __ldg(w4 + o4), w1 = __ldg(w4 + o4 + 1);
        const float4 a0 = __ldg(a4 + o4), a1 = __ldg(a4 + o4 + 1);
        const float4 b0 = __ldg(b4 + o4), b1 = __ldg(b4 + o4 + 1);
        acc[0] = fmaf(hv, fmaf(a0.x, b0.x, w0.x), acc[0]);
        acc[1] = fmaf(hv, fmaf(a0.y, b0.y, w0.y), acc[1]);
        acc[2] = fmaf(hv, fmaf(a0.z, b0.z, w0.z), acc[2]);
        acc[3] = fmaf(hv, fmaf(a0.w, b0.w, w0.w), acc[3]);
        acc[4] = fmaf(hv, fmaf(a1.x, b1.x, w1.x), acc[4]);
        acc[5] = fmaf(hv, fmaf(a1.y, b1.y, w1.y), acc[5]);
        acc[6] = fmaf(hv, fmaf(a1.z, b1.z, w1.z), acc[6]);
        acc[7] = fmaf(hv, fmaf(a1.w, b1.w, w1.w), acc[7]);
    }
    float4* s = &g_scratch4[((size_t)p * H + c0) / 4];
    s[0] = make_float4(acc[0], acc[1], acc[2], acc[3]);
    s[1] = make_float4(acc[4], acc[5], acc[6], acc[7]);
}

// ============ K2: reduce 256 partials per column, i2h + tanh -> h ============
__global__ __launch_bounds__(T2)
void k2_reduce(const float* __restrict__ x,
               const float* __restrict__ i2h_w,
               const float* __restrict__ i2h_b,
               float* __restrict__ out)
{
    __shared__ float4 sred[64][8];
    const int tid   = threadIdx.x;
    const int q     = tid & 7;         // local quad (4 cols): 8 quads = 32 cols
    const int s     = tid >> 3;        // slice 0..63
    const int qbase = blockIdx.x * 8;  // 32 columns per block

    float4 acc = make_float4(0.f, 0.f, 0.f, 0.f);
    #pragma unroll
    for (int p = s; p < NPART; p += 64) {   // 4 iterations
        const float4 v = g_scratch4[(size_t)p * (H / 4) + qbase + q];
        acc.x += v.x; acc.y += v.y; acc.z += v.z; acc.w += v.w;
    }
    sred[s][q] = acc;
    __syncthreads();

    if (tid < 8) {
        float4 pre = sred[0][tid];
        #pragma unroll
        for (int t = 1; t < 64; ++t) {
            const float4 v = sred[t][tid];
            pre.x += v.x; pre.y += v.y; pre.z += v.z; pre.w += v.w;
        }
        const int j0 = (qbase + tid) * 4;
        const float* prep = &pre.x;
        #pragma unroll
        for (int c = 0; c < 4; ++c) {
            const int j = j0 + c;
            float pr = i2h_b[j];
            #pragma unroll
            for (int kk = 0; kk < NIN; ++kk)
                pr = fmaf(x[kk], i2h_w[j * NIN + kk], pr);
            const float hj = tanhf(pr + prep[c]);
            out[5 + j] = hj;        // user-visible h
            g_h[j]     = hj;        // aligned shadow for K3
        }
    }
}

// ============ K3: blocks 0..1023 = hebb_new (lane-contiguous); last block = heads ============
__global__ __launch_bounds__(T3)
void k3_hebb(const float* __restrict__ hebb,
             const float* __restrict__ hidden,
             const float* __restrict__ eta,
             const float* __restrict__ h2o_w,
             const float* __restrict__ h2o_b,
             const float* __restrict__ h2v_w,
             const float* __restrict__ h2v_b,
             float* __restrict__ out)
{
    const int tid = threadIdx.x;

    if (blockIdx.x == GRID3) {
        // ----- heads: 5 dot products + softmax (deterministic fixed-order reduce) -----
        __shared__ float red[16][NA + 1];
        __shared__ float logits[NA + 1];
        const int warp = tid >> 5, lane = tid & 31;
        float acc[NA + 1] = {0.f, 0.f, 0.f, 0.f, 0.f};
        #pragma unroll
        for (int k = 0; k < H / T3; ++k) {
            const int j = tid + k * T3;
            const float hv = g_h[j];
            acc[0] = fmaf(hv, h2o_w[0 * H + j], acc[0]);
            acc[1] = fmaf(hv, h2o_w[1 * H + j], acc[1]);
            acc[2] = fmaf(hv, h2o_w[2 * H + j], acc[2]);
            acc[3] = fmaf(hv, h2o_w[3 * H + j], acc[3]);
            acc[4] = fmaf(hv, h2v_w[j],         acc[4]);
        }
        #pragma unroll
        for (int a = 0; a < NA + 1; ++a) {
            #pragma unroll
            for (int o = 16; o; o >>= 1)
                acc[a] += __shfl_xor_sync(0xffffffffu, acc[a], o);
            if (lane == 0) red[warp][a] = acc[a];
        }
        __syncthreads();
        if (tid < NA + 1) {
            float s = (tid < NA) ? h2o_b[tid] : h2v_b[0];
            #pragma unroll
            for (int wp = 0; wp < 16; ++wp) s += red[wp][tid];
            logits[tid] = s;
        }
        __syncthreads();
        if (tid == 0) {
            float m = logits[0];
            #pragma unroll
            for (int a = 1; a < NA; ++a) m = fmaxf(m, logits[a]);
            float e[NA], se = 0.f;
            #pragma unroll
            for (int a = 0; a < NA; ++a) { e[a] = expf(logits[a] - m); se += e[a]; }
            const float inv = 1.f / se;
            #pragma unroll
            for (int a = 0; a < NA; ++a) out[a] = e[a] * inv;
            out[NA] = logits[NA];
        }
        return;
    }

    // ----- hebb update: 16384 elements/block, lane-contiguous (full-line LDG/STG) -----
    const size_t base = (size_t)blockIdx.x * 16384;
    const float eta_v = __ldg(eta);
    const float om    = 1.f - eta_v;
    float* __restrict__ outp = out + 5 + H;     // 4B-misaligned -> scalar stores

    #pragma unroll 8
    for (int k = 0; k < 32; ++k) {
        const size_t n = base + (size_t)k * T3 + tid;
        const int i = (int)(n >> 12);           // row
        const int j = (int)(n & (H - 1));       // column
        const float hb = __ldg(hebb + n);
        outp[n] = fmaf(om, hb, eta_v * __ldg(&hidden[i]) * g_h[j]);
    }
}

extern "C" void kernel_launch(void* const* d_in, const int* in_sizes, int n_in,
                              void* d_out, int out_size)
{
    const float* x      = (const float*)d_in[0];
    const float* hidden = (const float*)d_in[1];
    const float* hebb   = (const float*)d_in[2];
    const float* i2h_w  = (const float*)d_in[3];
    const float* i2h_b  = (const float*)d_in[4];
    const float* w      = (const float*)d_in[5];
    const float* alpha  = (const float*)d_in[6];
    const float* eta    = (const float*)d_in[7];
    const float* h2o_w  = (const float*)d_in[8];
    const float* h2o_b  = (const float*)d_in[9];
    const float* h2v_w  = (const float*)d_in[10];
    const float* h2v_b  = (const float*)d_in[11];
    float* out = (float*)d_out;

    k1_partials<<<GRID1, T1>>>(hidden, w, alpha, hebb);
    k2_reduce  <<<GRID2, T2>>>(x, i2h_w, i2h_b, out);
    k3_hebb    <<<GRID3 + 1, T3>>>(hebb, hidden, eta, h2o_w, h2o_b, h2v_w, h2v_b, out);
}

// round 15
// speedup vs baseline: 1.2251x; 1.1926x over previous
#include <cuda_runtime.h>

#define H 4096
#define NIN 17
#define NA 4

#define GRID1 256           // K1: 16 rows per block
#define T1 512
#define NPART GRID1
#define GRID2 128           // K2: 32 cols per block
#define T2 512
#define GRID3 1024          // K3: 16384 elements per block (+1 head block)
#define T3 512

// persistent device scratch (static globals allowed; no runtime alloc)
__device__ float4 g_scratch4[NPART * H / 4];   // [p][col/4] partials, 4 MiB
__device__ __align__(16) float g_h[H];         // aligned shadow of h

// ---- 256-bit L2-eviction-hinted loads (sm_100+: hints require .v4.b64/.v8.b32) ----
__device__ __forceinline__ void ldg8_ef(const float* p, float v[8]) {
    unsigned long long r0, r1, r2, r3;
    asm volatile("ld.global.L2::evict_first.v4.b64 {%0,%1,%2,%3}, [%4];"
                 : "=l"(r0), "=l"(r1), "=l"(r2), "=l"(r3) : "l"(p));
    v[0] = __uint_as_float((unsigned)r0); v[1] = __uint_as_float((unsigned)(r0 >> 32));
    v[2] = __uint_as_float((unsigned)r1); v[3] = __uint_as_float((unsigned)(r1 >> 32));
    v[4] = __uint_as_float((unsigned)r2); v[5] = __uint_as_float((unsigned)(r2 >> 32));
    v[6] = __uint_as_float((unsigned)r3); v[7] = __uint_as_float((unsigned)(r3 >> 32));
}
__device__ __forceinline__ void ldg8_el(const float* p, float v[8]) {
    unsigned long long r0, r1, r2, r3;
    asm volatile("ld.global.L2::evict_last.v4.b64 {%0,%1,%2,%3}, [%4];"
                 : "=l"(r0), "=l"(r1), "=l"(r2), "=l"(r3) : "l"(p));
    v[0] = __uint_as_float((unsigned)r0); v[1] = __uint_as_float((unsigned)(r0 >> 32));
    v[2] = __uint_as_float((unsigned)r1); v[3] = __uint_as_float((unsigned)(r1 >> 32));
    v[4] = __uint_as_float((unsigned)r2); v[5] = __uint_as_float((unsigned)(r2 >> 32));
    v[6] = __uint_as_float((unsigned)r3); v[7] = __uint_as_float((unsigned)(r3 >> 32));
}

// ============ K1: partial sums of hidden @ (w + alpha*hebb), 16 rows/block ============
__global__ __launch_bounds__(T1)
void k1_partials(const float* __restrict__ hidden,
                 const float* __restrict__ w,
                 const float* __restrict__ alpha,
                 const float* __restrict__ hebb)
{
    const int tid = threadIdx.x;
    const int p   = blockIdx.x;
    const int i0  = p * 16;
    const int c0  = tid * 8;          // this thread's 8-column chunk (32B aligned)

    float acc[8] = {0.f, 0.f, 0.f, 0.f, 0.f, 0.f, 0.f, 0.f};
    #pragma unroll 8
    for (int r = 0; r < 16; ++r) {
        const float hv = __ldg(&hidden[i0 + r]);
        const size_t off = (size_t)(i0 + r) * H + c0;
        float wv[8], av[8], hb[8];
        ldg8_ef(w     + off, wv);
        ldg8_ef(alpha + off, av);
        ldg8_el(hebb  + off, hb);     // pin hebb toward L2 for K3's re-read
        #pragma unroll
        for (int c = 0; c < 8; ++c)
            acc[c] = fmaf(hv, fmaf(av[c], hb[c], wv[c]), acc[c]);
    }
    float4* s = &g_scratch4[((size_t)p * H + c0) / 4];
    s[0] = make_float4(acc[0], acc[1], acc[2], acc[3]);
    s[1] = make_float4(acc[4], acc[5], acc[6], acc[7]);
}

// ============ K2: reduce 256 partials per column, i2h + tanh -> h ============
__global__ __launch_bounds__(T2)
void k2_reduce(const float* __restrict__ x,
               const float* __restrict__ i2h_w,
               const float* __restrict__ i2h_b,
               float* __restrict__ out)
{
    __shared__ float4 sred[64][8];
    const int tid   = threadIdx.x;
    const int q     = tid & 7;         // local quad (4 cols): 8 quads = 32 cols
    const int s     = tid >> 3;        // slice 0..63
    const int qbase = blockIdx.x * 8;  // 32 columns per block

    float4 acc = make_float4(0.f, 0.f, 0.f, 0.f);
    #pragma unroll
    for (int p = s; p < NPART; p += 64) {   // 4 iterations
        const float4 v = __ldcs(&g_scratch4[(size_t)p * (H / 4) + qbase + q]);
        acc.x += v.x; acc.y += v.y; acc.z += v.z; acc.w += v.w;
    }
    sred[s][q] = acc;
    __syncthreads();

    if (tid < 8) {
        float4 pre = sred[0][tid];
        #pragma unroll
        for (int t = 1; t < 64; ++t) {
            const float4 v = sred[t][tid];
            pre.x += v.x; pre.y += v.y; pre.z += v.z; pre.w += v.w;
        }
        const int j0 = (qbase + tid) * 4;
        const float* prep = &pre.x;
        #pragma unroll
        for (int c = 0; c < 4; ++c) {
            const int j = j0 + c;
            float pr = i2h_b[j];
            #pragma unroll
            for (int kk = 0; kk < NIN; ++kk)
                pr = fmaf(x[kk], i2h_w[j * NIN + kk], pr);
            const float hj = tanhf(pr + prep[c]);
            out[5 + j] = hj;        // user-visible h
            g_h[j]     = hj;        // aligned shadow for K3
        }
    }
}

// ============ K3: blocks 0..1023 = hebb_new (lane-contiguous); last block = heads ============
__global__ __launch_bounds__(T3)
void k3_hebb(const float* __restrict__ hebb,
             const float* __restrict__ hidden,
             const float* __restrict__ eta,
             const float* __restrict__ h2o_w,
             const float* __restrict__ h2o_b,
             const float* __restrict__ h2v_w,
             const float* __restrict__ h2v_b,
             float* __restrict__ out)
{
    const int tid = threadIdx.x;

    if (blockIdx.x == GRID3) {
        // ----- heads: 5 dot products + softmax (deterministic fixed-order reduce) -----
        __shared__ float red[16][NA + 1];
        __shared__ float logits[NA + 1];
        const int warp = tid >> 5, lane = tid & 31;
        float acc[NA + 1] = {0.f, 0.f, 0.f, 0.f, 0.f};
        #pragma unroll
        for (int k = 0; k < H / T3; ++k) {
            const int j = tid + k * T3;
            const float hv = g_h[j];
            acc[0] = fmaf(hv, h2o_w[0 * H + j], acc[0]);
            acc[1] = fmaf(hv, h2o_w[1 * H + j], acc[1]);
            acc[2] = fmaf(hv, h2o_w[2 * H + j], acc[2]);
            acc[3] = fmaf(hv, h2o_w[3 * H + j], acc[3]);
            acc[4] = fmaf(hv, h2v_w[j],         acc[4]);
        }
        #pragma unroll
        for (int a = 0; a < NA + 1; ++a) {
            #pragma unroll
            for (int o = 16; o; o >>= 1)
                acc[a] += __shfl_xor_sync(0xffffffffu, acc[a], o);
            if (lane == 0) red[warp][a] = acc[a];
        }
        __syncthreads();
        if (tid < NA + 1) {
            float s = (tid < NA) ? h2o_b[tid] : h2v_b[0];
            #pragma unroll
            for (int wp = 0; wp < 16; ++wp) s += red[wp][tid];
            logits[tid] = s;
        }
        __syncthreads();
        if (tid == 0) {
            float m = logits[0];
            #pragma unroll
            for (int a = 1; a < NA; ++a) m = fmaxf(m, logits[a]);
            float e[NA], se = 0.f;
            #pragma unroll
            for (int a = 0; a < NA; ++a) { e[a] = expf(logits[a] - m); se += e[a]; }
            const float inv = 1.f / se;
            #pragma unroll
            for (int a = 0; a < NA; ++a) out[a] = e[a] * inv;
            out[NA] = logits[NA];
        }
        return;
    }

    // ----- hebb update: 16384 elements/block, lane-contiguous (full-line LDG/STG) -----
    // reversed order so K1's last-touched (L2-hottest) hebb rows are read first
    const size_t base = (size_t)(GRID3 - 1 - blockIdx.x) * 16384;
    const float eta_v = __ldg(eta);
    const float om    = 1.f - eta_v;
    float* __restrict__ outp = out + 5 + H;     // 4B-misaligned -> scalar stores

    #pragma unroll 8
    for (int k = 0; k < 32; ++k) {
        const size_t n = base + (size_t)k * T3 + tid;
        const int i = (int)(n >> 12);           // row
        const int j = (int)(n & (H - 1));       // column
        const float hb = __ldg(hebb + n);       // partial L2 hits via evict_last pin
        outp[n] = fmaf(om, hb, eta_v * __ldg(&hidden[i]) * g_h[j]);
    }
}

extern "C" void kernel_launch(void* const* d_in, const int* in_sizes, int n_in,
                              void* d_out, int out_size)
{
    const float* x      = (const float*)d_in[0];
    const float* hidden = (const float*)d_in[1];
    const float* hebb   = (const float*)d_in[2];
    const float* i2h_w  = (const float*)d_in[3];
    const float* i2h_b  = (const float*)d_in[4];
    const float* w      = (const float*)d_in[5];
    const float* alpha  = (const float*)d_in[6];
    const float* eta    = (const float*)d_in[7];
    const float* h2o_w  = (const float*)d_in[8];
    const float* h2o_b  = (const float*)d_in[9];
    const float* h2v_w  = (const float*)d_in[10];
    const float* h2v_b  = (const float*)d_in[11];
    float* out = (float*)d_out;

    k1_partials<<<GRID1, T1>>>(hidden, w, alpha, hebb);
    k2_reduce  <<<GRID2, T2>>>(x, i2h_w, i2h_b, out);
    k3_hebb    <<<GRID3 + 1, T3>>>(hebb, hidden, eta, h2o_w, h2o_b, h2v_w, h2v_b, out);
}

// round 16
// speedup vs baseline: 1.2656x; 1.0331x over previous
#include <cuda_runtime.h>

#define H 4096
#define NIN 17
#define NA 4

#define GRID1 256           // K1: 16 rows per block (4 MiB scratch)
#define T1 512
#define NPART GRID1
#define GRID2 128           // K2: 32 cols per block
#define T2 512
#define GRID3 1024          // K3: 16384 elements per block (+1 head block)
#define T3 512

// persistent device scratch (static globals allowed; no runtime alloc)
__device__ float4 g_scratch4[NPART * H / 4];   // [p][col/4] partials, 4 MiB
__device__ __align__(16) float g_h[H];         // aligned shadow of h

// ---- 256-bit L2-eviction-hinted loads (sm_100+: hints require .v4.b64/.v8.b32) ----
__device__ __forceinline__ void ldg8_ef(const float* p, float v[8]) {
    unsigned long long r0, r1, r2, r3;
    asm volatile("ld.global.L2::evict_first.v4.b64 {%0,%1,%2,%3}, [%4];"
                 : "=l"(r0), "=l"(r1), "=l"(r2), "=l"(r3) : "l"(p));
    v[0] = __uint_as_float((unsigned)r0); v[1] = __uint_as_float((unsigned)(r0 >> 32));
    v[2] = __uint_as_float((unsigned)r1); v[3] = __uint_as_float((unsigned)(r1 >> 32));
    v[4] = __uint_as_float((unsigned)r2); v[5] = __uint_as_float((unsigned)(r2 >> 32));
    v[6] = __uint_as_float((unsigned)r3); v[7] = __uint_as_float((unsigned)(r3 >> 32));
}
__device__ __forceinline__ void ldg8_el(const float* p, float v[8]) {
    unsigned long long r0, r1, r2, r3;
    asm volatile("ld.global.L2::evict_last.v4.b64 {%0,%1,%2,%3}, [%4];"
                 : "=l"(r0), "=l"(r1), "=l"(r2), "=l"(r3) : "l"(p));
    v[0] = __uint_as_float((unsigned)r0); v[1] = __uint_as_float((unsigned)(r0 >> 32));
    v[2] = __uint_as_float((unsigned)r1); v[3] = __uint_as_float((unsigned)(r1 >> 32));
    v[4] = __uint_as_float((unsigned)r2); v[5] = __uint_as_float((unsigned)(r2 >> 32));
    v[6] = __uint_as_float((unsigned)r3); v[7] = __uint_as_float((unsigned)(r3 >> 32));
}

// ============ K1: partial sums of hidden @ (w + alpha*hebb), 16 rows/block ============
__global__ __launch_bounds__(T1, 2)      // force <=64 regs -> 2 CTAs/SM
void k1_partials(const float* __restrict__ hidden,
                 const float* __restrict__ w,
                 const float* __restrict__ alpha,
                 const float* __restrict__ hebb)
{
    const int tid = threadIdx.x;
    const int p   = blockIdx.x;
    const int i0  = p * 16;
    const int c0  = tid * 8;          // this thread's 8-column chunk (32B aligned)

    float acc[8] = {0.f, 0.f, 0.f, 0.f, 0.f, 0.f, 0.f, 0.f};
    #pragma unroll 8
    for (int r = 0; r < 16; ++r) {
        const float hv = __ldg(&hidden[i0 + r]);
        const size_t off = (size_t)(i0 + r) * H + c0;
        float wv[8], av[8], hb[8];
        ldg8_ef(w     + off, wv);
        ldg8_ef(alpha + off, av);
        ldg8_el(hebb  + off, hb);     // pin hebb toward L2 for K3's re-read
        #pragma unroll
        for (int c = 0; c < 8; ++c)
            acc[c] = fmaf(hv, fmaf(av[c], hb[c], wv[c]), acc[c]);
    }
    float4* s = &g_scratch4[((size_t)p * H + c0) / 4];
    s[0] = make_float4(acc[0], acc[1], acc[2], acc[3]);
    s[1] = make_float4(acc[4], acc[5], acc[6], acc[7]);
}

// ============ K2: reduce 256 partials per column, i2h + tanh -> h ============
__global__ __launch_bounds__(T2)
void k2_reduce(const float* __restrict__ x,
               const float* __restrict__ i2h_w,
               const float* __restrict__ i2h_b,
               float* __restrict__ out)
{
    __shared__ float4 sred[64][8];
    const int tid   = threadIdx.x;
    const int q     = tid & 7;         // local quad (4 cols): 8 quads = 32 cols
    const int s     = tid >> 3;        // slice 0..63
    const int qbase = blockIdx.x * 8;  // 32 columns per block

    float4 acc = make_float4(0.f, 0.f, 0.f, 0.f);
    #pragma unroll
    for (int p = s; p < NPART; p += 64) {   // 4 iterations
        const float4 v = __ldcs(&g_scratch4[(size_t)p * (H / 4) + qbase + q]);
        acc.x += v.x; acc.y += v.y; acc.z += v.z; acc.w += v.w;
    }
    sred[s][q] = acc;
    __syncthreads();

    if (tid < 8) {
        float4 pre = sred[0][tid];
        #pragma unroll
        for (int t = 1; t < 64; ++t) {
            const float4 v = sred[t][tid];
            pre.x += v.x; pre.y += v.y; pre.z += v.z; pre.w += v.w;
        }
        const int j0 = (qbase + tid) * 4;
        const float* prep = &pre.x;
        #pragma unroll
        for (int c = 0; c < 4; ++c) {
            const int j = j0 + c;
            float pr = i2h_b[j];
            #pragma unroll
            for (int kk = 0; kk < NIN; ++kk)
                pr = fmaf(x[kk], i2h_w[j * NIN + kk], pr);
            const float hj = tanhf(pr + prep[c]);
            out[5 + j] = hj;        // user-visible h
            g_h[j]     = hj;        // aligned shadow for K3
        }
    }
}

// ============ K3: blocks 0..1023 = hebb_new (lane-contiguous); last block = heads ============
__global__ __launch_bounds__(T3)
void k3_hebb(const float* __restrict__ hebb,
             const float* __restrict__ hidden,
             const float* __restrict__ eta,
             const float* __restrict__ h2o_w,
             const float* __restrict__ h2o_b,
             const float* __restrict__ h2v_w,
             const float* __restrict__ h2v_b,
             float* __restrict__ out)
{
    const int tid = threadIdx.x;

    if (blockIdx.x == GRID3) {
        // ----- heads: 5 dot products + softmax (deterministic fixed-order reduce) -----
        __shared__ float red[16][NA + 1];
        __shared__ float logits[NA + 1];
        const int warp = tid >> 5, lane = tid & 31;
        float acc[NA + 1] = {0.f, 0.f, 0.f, 0.f, 0.f};
        #pragma unroll
        for (int k = 0; k < H / T3; ++k) {
            const int j = tid + k * T3;
            const float hv = g_h[j];
            acc[0] = fmaf(hv, h2o_w[0 * H + j], acc[0]);
            acc[1] = fmaf(hv, h2o_w[1 * H + j], acc[1]);
            acc[2] = fmaf(hv, h2o_w[2 * H + j], acc[2]);
            acc[3] = fmaf(hv, h2o_w[3 * H + j], acc[3]);
            acc[4] = fmaf(hv, h2v_w[j],         acc[4]);
        }
        #pragma unroll
        for (int a = 0; a < NA + 1; ++a) {
            #pragma unroll
            for (int o = 16; o; o >>= 1)
                acc[a] += __shfl_xor_sync(0xffffffffu, acc[a], o);
            if (lane == 0) red[warp][a] = acc[a];
        }
        __syncthreads();
        if (tid < NA + 1) {
            float s = (tid < NA) ? h2o_b[tid] : h2v_b[0];
            #pragma unroll
            for (int wp = 0; wp < 16; ++wp) s += red[wp][tid];
            logits[tid] = s;
        }
        __syncthreads();
        if (tid == 0) {
            float m = logits[0];
            #pragma unroll
            for (int a = 1; a < NA; ++a) m = fmaxf(m, logits[a]);
            float e[NA], se = 0.f;
            #pragma unroll
            for (int a = 0; a < NA; ++a) { e[a] = expf(logits[a] - m); se += e[a]; }
            const float inv = 1.f / se;
            #pragma unroll
            for (int a = 0; a < NA; ++a) out[a] = e[a] * inv;
            out[NA] = logits[NA];
        }
        return;
    }

    // ----- hebb update: 16384 elements/block, lane-contiguous (full-line LDG/STG) -----
    // reversed order so K1's last-touched (L2-hottest) hebb rows are read first
    const size_t base = (size_t)(GRID3 - 1 - blockIdx.x) * 16384;
    const float eta_v = __ldg(eta);
    const float om    = 1.f - eta_v;
    float* __restrict__ outp = out + 5 + H;     // 4B-misaligned -> scalar stores

    #pragma unroll 8
    for (int k = 0; k < 32; ++k) {
        const size_t n = base + (size_t)k * T3 + tid;
        const int i = (int)(n >> 12);           // row
        const int j = (int)(n & (H - 1));       // column
        const float hb = __ldg(hebb + n);       // partial L2 hits via evict_last pin
        outp[n] = fmaf(om, hb, eta_v * __ldg(&hidden[i]) * g_h[j]);
    }
}

extern "C" void kernel_launch(void* const* d_in, const int* in_sizes, int n_in,
                              void* d_out, int out_size)
{
    const float* x      = (const float*)d_in[0];
    const float* hidden = (const float*)d_in[1];
    const float* hebb   = (const float*)d_in[2];
    const float* i2h_w  = (const float*)d_in[3];
    const float* i2h_b  = (const float*)d_in[4];
    const float* w      = (const float*)d_in[5];
    const float* alpha  = (const float*)d_in[6];
    const float* eta    = (const float*)d_in[7];
    const float* h2o_w  = (const float*)d_in[8];
    const float* h2o_b  = (const float*)d_in[9];
    const float* h2v_w  = (const float*)d_in[10];
    const float* h2v_b  = (const float*)d_in[11];
    float* out = (float*)d_out;

    k1_partials<<<GRID1, T1>>>(hidden, w, alpha, hebb);
    k2_reduce  <<<GRID2, T2>>>(x, i2h_w, i2h_b, out);
    k3_hebb    <<<GRID3 + 1, T3>>>(hebb, hidden, eta, h2o_w, h2o_b, h2v_w, h2v_b, out);
}

// round 17
// speedup vs baseline: 1.3181x; 1.0414x over previous
#include <cuda_runtime.h>

#define H 4096
#define NIN 17
#define NA 4

#define GRID1 256           // K1: 16 rows per block (4 MiB scratch)
#define T1 512
#define NPART GRID1
#define GRID2 128           // K2: 32 cols per block
#define T2 512
#define GRID3 1024          // K3: 4 rows per block (+1 head block)
#define T3 512

// persistent device scratch (static globals allowed; no runtime alloc)
__device__ float4 g_scratch4[NPART * H / 4];   // [p][col/4] partials, 4 MiB
__device__ __align__(16) float g_h[H];         // aligned shadow of h

// ---- 256-bit L2-eviction-hinted loads (sm_100+: hints require .v4.b64/.v8.b32) ----
__device__ __forceinline__ void ldg8_ef(const float* p, float v[8]) {
    unsigned long long r0, r1, r2, r3;
    asm volatile("ld.global.L2::evict_first.v4.b64 {%0,%1,%2,%3}, [%4];"
                 : "=l"(r0), "=l"(r1), "=l"(r2), "=l"(r3) : "l"(p));
    v[0] = __uint_as_float((unsigned)r0); v[1] = __uint_as_float((unsigned)(r0 >> 32));
    v[2] = __uint_as_float((unsigned)r1); v[3] = __uint_as_float((unsigned)(r1 >> 32));
    v[4] = __uint_as_float((unsigned)r2); v[5] = __uint_as_float((unsigned)(r2 >> 32));
    v[6] = __uint_as_float((unsigned)r3); v[7] = __uint_as_float((unsigned)(r3 >> 32));
}
__device__ __forceinline__ void ldg8_el(const float* p, float v[8]) {
    unsigned long long r0, r1, r2, r3;
    asm volatile("ld.global.L2::evict_last.v4.b64 {%0,%1,%2,%3}, [%4];"
                 : "=l"(r0), "=l"(r1), "=l"(r2), "=l"(r3) : "l"(p));
    v[0] = __uint_as_float((unsigned)r0); v[1] = __uint_as_float((unsigned)(r0 >> 32));
    v[2] = __uint_as_float((unsigned)r1); v[3] = __uint_as_float((unsigned)(r1 >> 32));
    v[4] = __uint_as_float((unsigned)r2); v[5] = __uint_as_float((unsigned)(r2 >> 32));
    v[6] = __uint_as_float((unsigned)r3); v[7] = __uint_as_float((unsigned)(r3 >> 32));
}

// ============ K1: partial sums of hidden @ (w + alpha*hebb), 16 rows/block ============
__global__ __launch_bounds__(T1, 2)      // force <=64 regs -> 2 CTAs/SM
void k1_partials(const float* __restrict__ hidden,
                 const float* __restrict__ w,
                 const float* __restrict__ alpha,
                 const float* __restrict__ hebb)
{
    const int tid = threadIdx.x;
    const int p   = blockIdx.x;
    const int i0  = p * 16;
    const int c0  = tid * 8;          // this thread's 8-column chunk (32B aligned)

    float acc[8] = {0.f, 0.f, 0.f, 0.f, 0.f, 0.f, 0.f, 0.f};
    #pragma unroll 8
    for (int r = 0; r < 16; ++r) {
        const float hv = __ldg(&hidden[i0 + r]);
        const size_t off = (size_t)(i0 + r) * H + c0;
        float wv[8], av[8], hb[8];
        ldg8_ef(w     + off, wv);
        ldg8_ef(alpha + off, av);
        ldg8_el(hebb  + off, hb);     // pin hebb toward L2 for K3's re-read
        #pragma unroll
        for (int c = 0; c < 8; ++c)
            acc[c] = fmaf(hv, fmaf(av[c], hb[c], wv[c]), acc[c]);
    }
    float4* s = &g_scratch4[((size_t)p * H + c0) / 4];
    s[0] = make_float4(acc[0], acc[1], acc[2], acc[3]);
    s[1] = make_float4(acc[4], acc[5], acc[6], acc[7]);
}

// ============ K2: reduce 256 partials per column, i2h + tanh -> h ============
__global__ __launch_bounds__(T2)
void k2_reduce(const float* __restrict__ x,
               const float* __restrict__ i2h_w,
               const float* __restrict__ i2h_b,
               float* __restrict__ out)
{
    __shared__ float4 sred[64][8];
    const int tid   = threadIdx.x;
    const int q     = tid & 7;         // local quad (4 cols): 8 quads = 32 cols
    const int s     = tid >> 3;        // slice 0..63
    const int qbase = blockIdx.x * 8;  // 32 columns per block

    float4 acc = make_float4(0.f, 0.f, 0.f, 0.f);
    #pragma unroll
    for (int p = s; p < NPART; p += 64) {   // 4 iterations
        const float4 v = __ldcs(&g_scratch4[(size_t)p * (H / 4) + qbase + q]);
        acc.x += v.x; acc.y += v.y; acc.z += v.z; acc.w += v.w;
    }
    sred[s][q] = acc;
    __syncthreads();

    if (tid < 8) {
        float4 pre = sred[0][tid];
        #pragma unroll
        for (int t = 1; t < 64; ++t) {
            const float4 v = sred[t][tid];
            pre.x += v.x; pre.y += v.y; pre.z += v.z; pre.w += v.w;
        }
        const int j0 = (qbase + tid) * 4;
        const float* prep = &pre.x;
        #pragma unroll
        for (int c = 0; c < 4; ++c) {
            const int j = j0 + c;
            float pr = i2h_b[j];
            #pragma unroll
            for (int kk = 0; kk < NIN; ++kk)
                pr = fmaf(x[kk], i2h_w[j * NIN + kk], pr);
            const float hj = tanhf(pr + prep[c]);
            out[5 + j] = hj;        // user-visible h
            g_h[j]     = hj;        // aligned shadow for K3
        }
    }
}

// ============ K3: blocks 0..1023 = hebb_new (warp = quarter-row); last block = heads ============
__global__ __launch_bounds__(T3)
void k3_hebb(const float* __restrict__ hebb,
             const float* __restrict__ hidden,
             const float* __restrict__ eta,
             const float* __restrict__ h2o_w,
             const float* __restrict__ h2o_b,
             const float* __restrict__ h2v_w,
             const float* __restrict__ h2v_b,
             float* __restrict__ out)
{
    const int tid = threadIdx.x;

    if (blockIdx.x == GRID3) {
        // ----- heads: 5 dot products + softmax (deterministic fixed-order reduce) -----
        __shared__ float red[16][NA + 1];
        __shared__ float logits[NA + 1];
        const int warp = tid >> 5, lane = tid & 31;
        float acc[NA + 1] = {0.f, 0.f, 0.f, 0.f, 0.f};
        #pragma unroll
        for (int k = 0; k < H / T3; ++k) {
            const int j = tid + k * T3;
            const float hv = g_h[j];
            acc[0] = fmaf(hv, h2o_w[0 * H + j], acc[0]);
            acc[1] = fmaf(hv, h2o_w[1 * H + j], acc[1]);
            acc[2] = fmaf(hv, h2o_w[2 * H + j], acc[2]);
            acc[3] = fmaf(hv, h2o_w[3 * H + j], acc[3]);
            acc[4] = fmaf(hv, h2v_w[j],         acc[4]);
        }
        #pragma unroll
        for (int a = 0; a < NA + 1; ++a) {
            #pragma unroll
            for (int o = 16; o; o >>= 1)
                acc[a] += __shfl_xor_sync(0xffffffffu, acc[a], o);
            if (lane == 0) red[warp][a] = acc[a];
        }
        __syncthreads();
        if (tid < NA + 1) {
            float s = (tid < NA) ? h2o_b[tid] : h2v_b[0];
            #pragma unroll
            for (int wp = 0; wp < 16; ++wp) s += red[wp][tid];
            logits[tid] = s;
        }
        __syncthreads();
        if (tid == 0) {
            float m = logits[0];
            #pragma unroll
            for (int a = 1; a < NA; ++a) m = fmaxf(m, logits[a]);
            float e[NA], se = 0.f;
            #pragma unroll
            for (int a = 0; a < NA; ++a) { e[a] = expf(logits[a] - m); se += e[a]; }
            const float inv = 1.f / se;
            #pragma unroll
            for (int a = 0; a < NA; ++a) out[a] = e[a] * inv;
            out[NA] = logits[NA];
        }
        return;
    }

    // ----- hebb update: block = 4 rows, warp = quarter-row (1024 consecutive floats) -----
    __shared__ __align__(16) float sh_h[H];     // 16 KB copy of h
    #pragma unroll
    for (int k = 0; k < H / T3; ++k)
        sh_h[tid + k * T3] = g_h[tid + k * T3];
    __syncthreads();

    // reversed order so K1's last-touched (L2-hottest) hebb rows are read first
    const int blk  = GRID3 - 1 - blockIdx.x;
    const int warp = tid >> 5, lane = tid & 31;
    const int row  = blk * 4 + (warp >> 2);     // 4 rows per block
    const int jseg = (warp & 3) * 1024;         // quarter-row segment

    const float eta_v = __ldg(eta);
    const float om    = 1.f - eta_v;
    const float ev    = eta_v * __ldg(&hidden[row]);   // hoisted: 1 load per warp
    const size_t rowbase = (size_t)row * H + jseg;
    const float* __restrict__ hp = hebb + rowbase;
    float* __restrict__ op = out + 5 + H + rowbase;    // 4B-misaligned -> scalar stores
    const float* __restrict__ shp = sh_h + jseg;

    #pragma unroll 8
    for (int k = 0; k < 32; ++k) {
        const int o = k * 32 + lane;
        const float hb = __ldg(hp + o);         // partial L2 hits via evict_last pin
        op[o] = fmaf(om, hb, ev * shp[o]);
    }
}

extern "C" void kernel_launch(void* const* d_in, const int* in_sizes, int n_in,
                              void* d_out, int out_size)
{
    const float* x      = (const float*)d_in[0];
    const float* hidden = (const float*)d_in[1];
    const float* hebb   = (const float*)d_in[2];
    const float* i2h_w  = (const float*)d_in[3];
    const float* i2h_b  = (const float*)d_in[4];
    const float* w      = (const float*)d_in[5];
    const float* alpha  = (const float*)d_in[6];
    const float* eta    = (const float*)d_in[7];
    const float* h2o_w  = (const float*)d_in[8];
    const float* h2o_b  = (const float*)d_in[9];
    const float* h2v_w  = (const float*)d_in[10];
    const float* h2v_b  = (const float*)d_in[11];
    float* out = (float*)d_out;

    k1_partials<<<GRID1, T1>>>(hidden, w, alpha, hebb);
    k2_reduce  <<<GRID2, T2>>>(x, i2h_w, i2h_b, out);
    k3_hebb    <<<GRID3 + 1, T3>>>(hebb, hidden, eta, h2o_w, h2o_b, h2v_w, h2v_b, out);
}